// round 2
// baseline (speedup 1.0000x reference)
#include <cuda_runtime.h>
#include <math.h>

// Problem-fixed capacities (from reference: N_NODES=50000, N_EDGES=800000)
#define NNODES 50000
#define NEDGES 800000
#define ETMAX (NEDGES + NNODES)

// ---------------- scratch (device globals; no allocation allowed) ----------
__device__ __align__(16) float g_h[(size_t)NNODES * 256];   // post-GEMM features
__device__ __align__(16) float g_out[(size_t)NNODES * 256]; // aggregated output / next input
__device__ float g_s[NNODES * 4];                // per (node,head) src attn score
__device__ float g_d[NNODES * 4];                // per (node,head) dst attn score
__device__ float g_emax[NNODES * 4];             // segment max
__device__ float g_den[NNODES * 4];              // segment sum of exp
__device__ float g_esc[(size_t)ETMAX * 4];       // per (edge,head) raw score
__device__ float g_eexp[(size_t)ETMAX * 4];      // per (edge,head) exp(score-max)
__device__ int   g_deg[NNODES];
__device__ int   g_off[NNODES + 1];
__device__ int   g_cur[NNODES];
__device__ int   g_csrc[ETMAX];                  // CSR-by-dst: source node
__device__ int   g_ceid[ETMAX];                  // CSR-by-dst: edge id

// ---------------- helpers ----------------
__device__ __forceinline__ void atomicMaxF(float* addr, float v) {
    // monotone bit trick; init = -inf
    if (v >= 0.f) atomicMax((int*)addr, __float_as_int(v));
    else          atomicMin((unsigned int*)addr, __float_as_uint(v));
}

// ---------------- GEMM: C[M,N] = A[M,K] @ B[K,N], fp32, 128x128x8 tiles ----
__global__ __launch_bounds__(256) void gemm_k(
    const float* __restrict__ A, const float* __restrict__ B, float* __restrict__ C,
    int M, int N, int K) {
  __shared__ __align__(16) float As[8][128];
  __shared__ __align__(16) float Bs[8][128];
  const int tid = threadIdx.x;
  const int tx = tid & 15;
  const int ty = tid >> 4;
  const int rowBase = blockIdx.y * 128;
  const int colBase = blockIdx.x * 128;
  float acc[8][8];
#pragma unroll
  for (int i = 0; i < 8; i++)
#pragma unroll
    for (int j = 0; j < 8; j++) acc[i][j] = 0.f;

  const int ar  = tid >> 1;          // 0..127
  const int akq = (tid & 1) * 4;     // 0 or 4
  const int bkr = tid >> 5;          // 0..7
  const int bnc = (tid & 31) * 4;    // 0..124

  for (int k0 = 0; k0 < K; k0 += 8) {
    float4 av = make_float4(0.f, 0.f, 0.f, 0.f);
    if (rowBase + ar < M)
      av = *reinterpret_cast<const float4*>(&A[(size_t)(rowBase + ar) * K + k0 + akq]);
    As[akq + 0][ar] = av.x;
    As[akq + 1][ar] = av.y;
    As[akq + 2][ar] = av.z;
    As[akq + 3][ar] = av.w;

    float4 bv = make_float4(0.f, 0.f, 0.f, 0.f);
    const int col = colBase + bnc;
    const size_t brow = (size_t)(k0 + bkr) * N;
    if (col + 3 < N) {
      bv = *reinterpret_cast<const float4*>(&B[brow + col]);
    } else {
      if (col + 0 < N) bv.x = B[brow + col + 0];
      if (col + 1 < N) bv.y = B[brow + col + 1];
      if (col + 2 < N) bv.z = B[brow + col + 2];
      if (col + 3 < N) bv.w = B[brow + col + 3];
    }
    *reinterpret_cast<float4*>(&Bs[bkr][bnc]) = bv;
    __syncthreads();
#pragma unroll
    for (int kk = 0; kk < 8; kk++) {
      float a[8], b[8];
#pragma unroll
      for (int i = 0; i < 8; i++) a[i] = As[kk][ty * 8 + i];
#pragma unroll
      for (int j = 0; j < 8; j++) b[j] = Bs[kk][tx * 8 + j];
#pragma unroll
      for (int i = 0; i < 8; i++)
#pragma unroll
        for (int j = 0; j < 8; j++) acc[i][j] = fmaf(a[i], b[j], acc[i][j]);
    }
    __syncthreads();
  }
#pragma unroll
  for (int i = 0; i < 8; i++) {
    const int row = rowBase + ty * 8 + i;
    if (row >= M) continue;
#pragma unroll
    for (int j = 0; j < 8; j++) {
      const int c = colBase + tx * 8 + j;
      if (c < N) C[(size_t)row * N + c] = acc[i][j];
    }
  }
}

// ---------------- CSR build (once per launch; graph identical for 3 layers) -
__global__ void k_zero_deg(int n) {
  int i = blockIdx.x * blockDim.x + threadIdx.x;
  if (i < n) g_deg[i] = 0;
}

__global__ void k_count(const int* __restrict__ ei, int E, int n) {
  int e = blockIdx.x * blockDim.x + threadIdx.x;
  if (e >= E + n) return;
  int dst = (e < E) ? ei[E + e] : (e - E);
  atomicAdd(&g_deg[dst], 1);
}

__global__ void k_scan(int n) {
  __shared__ int sh[1024];
  __shared__ int carry;
  const int tid = threadIdx.x;
  if (tid == 0) carry = 0;
  __syncthreads();
  for (int base = 0; base < n; base += 1024) {
    const int i = base + tid;
    const int v = (i < n) ? g_deg[i] : 0;
    sh[tid] = v;
    __syncthreads();
    for (int s = 1; s < 1024; s <<= 1) {
      int t = (tid >= s) ? sh[tid - s] : 0;
      __syncthreads();
      sh[tid] += t;
      __syncthreads();
    }
    const int incl = sh[tid];
    const int excl = incl - v;
    const int c = carry;
    if (i < n) { g_off[i] = c + excl; g_cur[i] = c + excl; }
    __syncthreads();
    if (tid == 1023) carry = c + sh[1023];
    __syncthreads();
  }
  if (threadIdx.x == 0) g_off[n] = carry;
}

__global__ void k_scatter(const int* __restrict__ ei, int E, int n) {
  int e = blockIdx.x * blockDim.x + threadIdx.x;
  if (e >= E + n) return;
  int src, dst;
  if (e < E) { src = ei[e]; dst = ei[E + e]; }
  else       { src = dst = e - E; }
  const int pos = atomicAdd(&g_cur[dst], 1);
  g_csrc[pos] = src;
  g_ceid[pos] = e;
}

// ---------------- attention pieces ----------------
__global__ void k_init_soft(int cnt) {
  int i = blockIdx.x * blockDim.x + threadIdx.x;
  if (i < cnt) { g_emax[i] = -INFINITY; g_den[i] = 0.f; }
}

// s[n,h] = <h[n,h,:], a_src[h,:]>, d likewise. One warp per (node,head).
__global__ void k_node_attn(const float* __restrict__ h,
                            const float* __restrict__ asrc,
                            const float* __restrict__ adst,
                            int n, int H, int C) {
  const int w = (blockIdx.x * blockDim.x + threadIdx.x) >> 5;
  const int lane = threadIdx.x & 31;
  if (w >= n * H) return;
  const int node = w / H;
  const int hd = w - node * H;
  const float* hp = h + (size_t)node * H * C + (size_t)hd * C;
  float ss = 0.f, dd = 0.f;
  for (int c = lane; c < C; c += 32) {
    const float v = hp[c];
    ss = fmaf(v, asrc[hd * C + c], ss);
    dd = fmaf(v, adst[hd * C + c], dd);
  }
#pragma unroll
  for (int o = 16; o; o >>= 1) {
    ss += __shfl_xor_sync(0xffffffffu, ss, o);
    dd += __shfl_xor_sync(0xffffffffu, dd, o);
  }
  if (lane == 0) { g_s[w] = ss; g_d[w] = dd; }
}

__global__ void k_edge_score(const int* __restrict__ ei, int E, int n, int H) {
  const int t = blockIdx.x * blockDim.x + threadIdx.x;
  const int ET = E + n;
  if (t >= ET * H) return;
  const int e = t / H;
  const int hd = t - e * H;
  int src, dst;
  if (e < E) { src = ei[e]; dst = ei[E + e]; }
  else       { src = dst = e - E; }
  float v = g_s[src * H + hd] + g_d[dst * H + hd];
  v = (v > 0.f) ? v : 0.2f * v;               // leaky relu, slope 0.2
  g_esc[t] = v;
  atomicMaxF(&g_emax[dst * H + hd], v);
}

__global__ void k_edge_exp(const int* __restrict__ ei, int E, int n, int H) {
  const int t = blockIdx.x * blockDim.x + threadIdx.x;
  const int ET = E + n;
  if (t >= ET * H) return;
  const int e = t / H;
  const int hd = t - e * H;
  int dst;
  if (e < E) dst = ei[E + e];
  else       dst = e - E;
  const float ex = expf(g_esc[t] - g_emax[dst * H + hd]);
  g_eexp[t] = ex;
  atomicAdd(&g_den[dst * H + hd], ex);
}

// ---------------- aggregation ----------------
// Layers 1/2: F=256 (H=4, C=64). One block per dst node, thread = one channel.
// Fused: +bias, batchnorm, relu.
__global__ __launch_bounds__(256) void k_agg256(
    const float* __restrict__ h,
    const float* __restrict__ bias, const float* __restrict__ gamma,
    const float* __restrict__ beta, const float* __restrict__ mean,
    const float* __restrict__ var, float* __restrict__ out, int n) {
  const int node = blockIdx.x;
  if (node >= n) return;
  const int c = threadIdx.x;
  const int hd = c >> 6;
  const float invden = 1.f / g_den[node * 4 + hd];
  const int k0 = g_off[node];
  const int k1 = g_off[node + 1];
  float acc = 0.f;
  for (int k = k0; k < k1; k++) {
    const int src = g_csrc[k];
    const int eid = g_ceid[k];
    const float alpha = g_eexp[(size_t)eid * 4 + hd] * invden;
    acc = fmaf(alpha, h[(size_t)src * 256 + c], acc);
  }
  float o = acc + bias[c];
  o = (o - mean[c]) * rsqrtf(var[c] + 1e-5f) * gamma[c] + beta[c];
  out[(size_t)node * 256 + c] = fmaxf(o, 0.f);
}

// Layer 3: F=16 (H=1). 16 nodes per block, 16 channels each. Out = acc + bias.
__global__ __launch_bounds__(256) void k_agg16(
    const float* __restrict__ h, const float* __restrict__ bias,
    float* __restrict__ out, int n) {
  const int local = threadIdx.x >> 4;
  const int c = threadIdx.x & 15;
  const int node = blockIdx.x * 16 + local;
  if (node >= n) return;
  const float invden = 1.f / g_den[node];
  const int k0 = g_off[node];
  const int k1 = g_off[node + 1];
  float acc = 0.f;
  for (int k = k0; k < k1; k++) {
    const int src = g_csrc[k];
    const int eid = g_ceid[k];
    acc = fmaf(g_eexp[eid] * invden, h[(size_t)src * 16 + c], acc);
  }
  out[(size_t)node * 16 + c] = acc + bias[c];
}

// ---------------- host ----------------
extern "C" void kernel_launch(void* const* d_in, const int* in_sizes, int n_in,
                              void* d_out, int out_size) {
  const float* x   = (const float*)d_in[0];
  const int*   ei  = (const int*)d_in[1];       // int32! (JAX x64 disabled)
  const float* W1  = (const float*)d_in[2];
  const float* as1 = (const float*)d_in[3];
  const float* ad1 = (const float*)d_in[4];
  const float* b1  = (const float*)d_in[5];
  const float* g1  = (const float*)d_in[6];
  const float* be1 = (const float*)d_in[7];
  const float* m1  = (const float*)d_in[8];
  const float* v1  = (const float*)d_in[9];
  const float* W2  = (const float*)d_in[10];
  const float* as2 = (const float*)d_in[11];
  const float* ad2 = (const float*)d_in[12];
  const float* b2  = (const float*)d_in[13];
  const float* g2  = (const float*)d_in[14];
  const float* be2 = (const float*)d_in[15];
  const float* m2  = (const float*)d_in[16];
  const float* v2  = (const float*)d_in[17];
  const float* W3  = (const float*)d_in[18];
  const float* as3 = (const float*)d_in[19];
  const float* ad3 = (const float*)d_in[20];
  const float* b3  = (const float*)d_in[21];

  const int n  = in_sizes[0] / 128;    // 50000
  const int E  = in_sizes[1] / 2;      // 800000
  const int ET = E + n;

  float* p_h;   cudaGetSymbolAddress((void**)&p_h,   g_h);
  float* p_out; cudaGetSymbolAddress((void**)&p_out, g_out);

  const int TB = 256;
  const int edgeBlocks = (ET + TB - 1) / TB;

  // ---- CSR by dst (shared by all 3 layers) ----
  k_zero_deg<<<(n + TB - 1) / TB, TB>>>(n);
  k_count<<<edgeBlocks, TB>>>(ei, E, n);
  k_scan<<<1, 1024>>>(n);
  k_scatter<<<edgeBlocks, TB>>>(ei, E, n);

  // ---- layer 1: GAT(128 -> 64x4) + BN + ReLU ----
  {
    dim3 grid((256 + 127) / 128, (n + 127) / 128);
    gemm_k<<<grid, 256>>>(x, W1, p_h, n, 256, 128);
    k_init_soft<<<(n * 4 + TB - 1) / TB, TB>>>(n * 4);
    k_node_attn<<<(n * 4 * 32 + TB - 1) / TB, TB>>>(p_h, as1, ad1, n, 4, 64);
    k_edge_score<<<((size_t)ET * 4 + TB - 1) / TB, TB>>>(ei, E, n, 4);
    k_edge_exp<<<((size_t)ET * 4 + TB - 1) / TB, TB>>>(ei, E, n, 4);
    k_agg256<<<n, 256>>>(p_h, b1, g1, be1, m1, v1, p_out, n);
  }

  // ---- layer 2: GAT(256 -> 64x4) + BN + ReLU ----
  {
    dim3 grid((256 + 127) / 128, (n + 127) / 128);
    gemm_k<<<grid, 256>>>(p_out, W2, p_h, n, 256, 256);
    k_init_soft<<<(n * 4 + TB - 1) / TB, TB>>>(n * 4);
    k_node_attn<<<(n * 4 * 32 + TB - 1) / TB, TB>>>(p_h, as2, ad2, n, 4, 64);
    k_edge_score<<<((size_t)ET * 4 + TB - 1) / TB, TB>>>(ei, E, n, 4);
    k_edge_exp<<<((size_t)ET * 4 + TB - 1) / TB, TB>>>(ei, E, n, 4);
    k_agg256<<<n, 256>>>(p_h, b2, g2, be2, m2, v2, p_out, n);
  }

  // ---- layer 3: GAT(256 -> 16, single head, no concat) ----
  {
    dim3 grid((16 + 127) / 128, (n + 127) / 128);
    gemm_k<<<grid, 256>>>(p_out, W3, p_h, n, 16, 256);
    k_init_soft<<<(n + TB - 1) / TB, TB>>>(n);
    k_node_attn<<<(n * 32 + TB - 1) / TB, TB>>>(p_h, as3, ad3, n, 1, 16);
    k_edge_score<<<(ET + TB - 1) / TB, TB>>>(ei, E, n, 1);
    k_edge_exp<<<(ET + TB - 1) / TB, TB>>>(ei, E, n, 1);
    k_agg16<<<(n + 15) / 16, 256>>>(p_h, b3, (float*)d_out, n);
  }
}

// round 3
// speedup vs baseline: 1.5197x; 1.5197x over previous
#include <cuda_runtime.h>
#include <math.h>

#define NNODES 50000
#define NEDGES 800000
#define ETMAX (NEDGES + NNODES)

// ---------------- scratch (device globals; no allocation allowed) ----------
__device__ __align__(16) float g_h[(size_t)NNODES * 256];   // post-GEMM features
__device__ __align__(16) float g_out[(size_t)NNODES * 256]; // aggregated output / next input
__device__ __align__(16) float g_s[NNODES * 4];             // per (node,head) src score
__device__ __align__(16) float g_d[NNODES * 4];             // per (node,head) dst score
__device__ __align__(16) float g_den[NNODES * 4];           // segment sum of exp
__device__ __align__(16) float g_eexp[(size_t)ETMAX * 4];   // per (edge,head) exp(score)
__device__ int   g_deg[NNODES];
__device__ int   g_off[NNODES + 1];
__device__ int   g_cur[NNODES];
__device__ int   g_csrc[ETMAX];                  // CSR-by-dst: source node
__device__ int   g_ceid[ETMAX];                  // CSR-by-dst: edge id

// ---------------- GEMM: C[M,N] = A[M,K] @ B[K,N]; N multiple of 128, K of 16
__global__ __launch_bounds__(256) void gemm_k(
    const float* __restrict__ A, const float* __restrict__ B, float* __restrict__ C,
    int M, int N, int K) {
  __shared__ __align__(16) float As[16][128];
  __shared__ __align__(16) float Bs[16][128];
  const int tid = threadIdx.x;
  const int tx = tid & 15;
  const int ty = tid >> 4;
  const int rowBase = blockIdx.y * 128;
  const int colBase = blockIdx.x * 128;

  // A-tile load map: row = tid>>1 (0..127), kq = (tid&1)*8 -> 2 float4 along K
  const int ar  = tid >> 1;
  const int akq = (tid & 1) * 8;
  // B-tile load map: rows bkr and bkr+8, col = (tid&31)*4
  const int bkr = tid >> 5;
  const int bnc = (tid & 31) * 4;

  float acc[8][8];
#pragma unroll
  for (int i = 0; i < 8; i++)
#pragma unroll
    for (int j = 0; j < 8; j++) acc[i][j] = 0.f;

  const bool aok = (rowBase + ar) < M;
  const float* Aptr = A + (size_t)(rowBase + ar) * K + akq;
  const float* Bptr = B + (size_t)bkr * N + colBase + bnc;

  float4 a0 = make_float4(0,0,0,0), a1 = a0, b0, b1;
  if (aok) {
    a0 = *reinterpret_cast<const float4*>(Aptr + 0);
    a1 = *reinterpret_cast<const float4*>(Aptr + 4);
  }
  b0 = *reinterpret_cast<const float4*>(Bptr);
  b1 = *reinterpret_cast<const float4*>(Bptr + (size_t)8 * N);

  const int T = K / 16;
  for (int t = 0; t < T; t++) {
    // store staged regs to smem
    As[akq + 0][ar] = a0.x; As[akq + 1][ar] = a0.y;
    As[akq + 2][ar] = a0.z; As[akq + 3][ar] = a0.w;
    As[akq + 4][ar] = a1.x; As[akq + 5][ar] = a1.y;
    As[akq + 6][ar] = a1.z; As[akq + 7][ar] = a1.w;
    *reinterpret_cast<float4*>(&Bs[bkr][bnc]) = b0;
    *reinterpret_cast<float4*>(&Bs[bkr + 8][bnc]) = b1;
    __syncthreads();

    if (t + 1 < T) {  // prefetch next tile
      const float* Ap = Aptr + (t + 1) * 16;
      if (aok) {
        a0 = *reinterpret_cast<const float4*>(Ap + 0);
        a1 = *reinterpret_cast<const float4*>(Ap + 4);
      }
      const float* Bp = Bptr + (size_t)(t + 1) * 16 * N;
      b0 = *reinterpret_cast<const float4*>(Bp);
      b1 = *reinterpret_cast<const float4*>(Bp + (size_t)8 * N);
    }

#pragma unroll
    for (int kk = 0; kk < 16; kk++) {
      float a[8], b[8];
#pragma unroll
      for (int i = 0; i < 8; i++) a[i] = As[kk][ty * 8 + i];
#pragma unroll
      for (int j = 0; j < 8; j++) b[j] = Bs[kk][tx * 8 + j];
#pragma unroll
      for (int i = 0; i < 8; i++)
#pragma unroll
        for (int j = 0; j < 8; j++) acc[i][j] = fmaf(a[i], b[j], acc[i][j]);
    }
    __syncthreads();
  }
#pragma unroll
  for (int i = 0; i < 8; i++) {
    const int row = rowBase + ty * 8 + i;
    if (row >= M) continue;
    float4* cp = reinterpret_cast<float4*>(&C[(size_t)row * N + colBase + tx * 8]);
    cp[0] = make_float4(acc[i][0], acc[i][1], acc[i][2], acc[i][3]);
    cp[1] = make_float4(acc[i][4], acc[i][5], acc[i][6], acc[i][7]);
  }
}

// ---------------- GEMM for layer 3: N=16, K=256 (memory-bound) --------------
__global__ __launch_bounds__(256) void gemm_n16(
    const float* __restrict__ A, const float* __restrict__ B, float* __restrict__ C,
    int M) {
  const int t = blockIdx.x * blockDim.x + threadIdx.x;
  const int row = t >> 4;
  const int nc = t & 15;
  if (row >= M) return;
  const float* a = A + (size_t)row * 256;
  float acc = 0.f;
#pragma unroll 8
  for (int k = 0; k < 256; k += 4) {
    const float4 av = *reinterpret_cast<const float4*>(a + k);
    acc = fmaf(av.x, B[(k + 0) * 16 + nc], acc);
    acc = fmaf(av.y, B[(k + 1) * 16 + nc], acc);
    acc = fmaf(av.z, B[(k + 2) * 16 + nc], acc);
    acc = fmaf(av.w, B[(k + 3) * 16 + nc], acc);
  }
  C[(size_t)row * 16 + nc] = acc;
}

// ---------------- CSR build --------------------------------------------------
__global__ void k_zero_deg(int n) {
  int i = blockIdx.x * blockDim.x + threadIdx.x;
  if (i < n) g_deg[i] = 0;
}

__global__ void k_count(const int* __restrict__ ei, int E, int n) {
  int e = blockIdx.x * blockDim.x + threadIdx.x;
  if (e >= E + n) return;
  int dst = (e < E) ? ei[E + e] : (e - E);
  atomicAdd(&g_deg[dst], 1);
}

__global__ void k_scan(int n) {
  __shared__ int sh[1024];
  __shared__ int carry;
  const int tid = threadIdx.x;
  if (tid == 0) carry = 0;
  __syncthreads();
  for (int base = 0; base < n; base += 1024) {
    const int i = base + tid;
    const int v = (i < n) ? g_deg[i] : 0;
    sh[tid] = v;
    __syncthreads();
    for (int s = 1; s < 1024; s <<= 1) {
      int t = (tid >= s) ? sh[tid - s] : 0;
      __syncthreads();
      sh[tid] += t;
      __syncthreads();
    }
    const int incl = sh[tid];
    const int excl = incl - v;
    const int c = carry;
    if (i < n) { g_off[i] = c + excl; g_cur[i] = c + excl; }
    __syncthreads();
    if (tid == 1023) carry = c + sh[1023];
    __syncthreads();
  }
  if (threadIdx.x == 0) g_off[n] = carry;
}

__global__ void k_scatter(const int* __restrict__ ei, int E, int n) {
  int e = blockIdx.x * blockDim.x + threadIdx.x;
  if (e >= E + n) return;
  int src, dst;
  if (e < E) { src = ei[e]; dst = ei[E + e]; }
  else       { src = dst = e - E; }
  const int pos = atomicAdd(&g_cur[dst], 1);
  g_csrc[pos] = src;
  g_ceid[pos] = e;
}

// ---------------- attention ---------------------------------------------
__global__ void k_zero_den(int cnt) {
  int i = blockIdx.x * blockDim.x + threadIdx.x;
  if (i < cnt) g_den[i] = 0.f;
}

// s[n,h] = <h[n,h,:], a_src[h,:]>, d likewise. One warp per (node,head).
__global__ void k_node_attn(const float* __restrict__ h,
                            const float* __restrict__ asrc,
                            const float* __restrict__ adst,
                            int n, int H, int C) {
  const int w = (blockIdx.x * blockDim.x + threadIdx.x) >> 5;
  const int lane = threadIdx.x & 31;
  if (w >= n * H) return;
  const int node = w / H;
  const int hd = w - node * H;
  const float* hp = h + (size_t)node * H * C + (size_t)hd * C;
  float ss = 0.f, dd = 0.f;
  for (int c = lane; c < C; c += 32) {
    const float v = hp[c];
    ss = fmaf(v, asrc[hd * C + c], ss);
    dd = fmaf(v, adst[hd * C + c], dd);
  }
#pragma unroll
  for (int o = 16; o; o >>= 1) {
    ss += __shfl_xor_sync(0xffffffffu, ss, o);
    dd += __shfl_xor_sync(0xffffffffu, dd, o);
  }
  if (lane == 0) { g_s[w] = ss; g_d[w] = dd; }
}

// Fused edge pass (H=4): score -> leakyrelu -> exp (no max shift; scores are
// O(1) so exp is safe and alpha is mathematically identical) -> atomic denom.
__global__ void k_edge4(const int* __restrict__ ei, int E, int n) {
  const int e = blockIdx.x * blockDim.x + threadIdx.x;
  const int ET = E + n;
  if (e >= ET) return;
  int src, dst;
  if (e < E) { src = ei[e]; dst = ei[E + e]; }
  else       { src = dst = e - E; }
  const float4 s = *reinterpret_cast<const float4*>(&g_s[src * 4]);
  const float4 d = *reinterpret_cast<const float4*>(&g_d[dst * 4]);
  float v0 = s.x + d.x, v1 = s.y + d.y, v2 = s.z + d.z, v3 = s.w + d.w;
  v0 = (v0 > 0.f) ? v0 : 0.2f * v0;
  v1 = (v1 > 0.f) ? v1 : 0.2f * v1;
  v2 = (v2 > 0.f) ? v2 : 0.2f * v2;
  v3 = (v3 > 0.f) ? v3 : 0.2f * v3;
  const float e0 = __expf(v0), e1 = __expf(v1), e2 = __expf(v2), e3 = __expf(v3);
  *reinterpret_cast<float4*>(&g_eexp[(size_t)e * 4]) = make_float4(e0, e1, e2, e3);
  atomicAdd(&g_den[dst * 4 + 0], e0);
  atomicAdd(&g_den[dst * 4 + 1], e1);
  atomicAdd(&g_den[dst * 4 + 2], e2);
  atomicAdd(&g_den[dst * 4 + 3], e3);
}

// Fused edge pass (H=1), eexp stored stride-1.
__global__ void k_edge1(const int* __restrict__ ei, int E, int n) {
  const int e = blockIdx.x * blockDim.x + threadIdx.x;
  const int ET = E + n;
  if (e >= ET) return;
  int src, dst;
  if (e < E) { src = ei[e]; dst = ei[E + e]; }
  else       { src = dst = e - E; }
  float v = g_s[src] + g_d[dst];
  v = (v > 0.f) ? v : 0.2f * v;
  const float ex = __expf(v);
  g_eexp[e] = ex;
  atomicAdd(&g_den[dst], ex);
}

// ---------------- aggregation ----------------
// Layers 1/2: F=256. 64 threads per node (float4 channels), 4 nodes per block.
// Fused: +bias, batchnorm, relu.
__global__ __launch_bounds__(256) void k_agg256(
    const float* __restrict__ h,
    const float* __restrict__ bias, const float* __restrict__ gamma,
    const float* __restrict__ beta, const float* __restrict__ mean,
    const float* __restrict__ var, float* __restrict__ out, int n) {
  const int grp = threadIdx.x >> 6;              // 0..3
  const int c4  = threadIdx.x & 63;              // float4 index: channels c4*4..+3
  const int node = blockIdx.x * 4 + grp;
  if (node >= n) return;
  const int c = c4 * 4;
  const int hd = c >> 6;
  const float invden = 1.f / g_den[node * 4 + hd];
  const int k0 = g_off[node];
  const int k1 = g_off[node + 1];
  float4 acc = make_float4(0.f, 0.f, 0.f, 0.f);
  for (int k = k0; k < k1; k++) {
    const int src = g_csrc[k];
    const int eid = g_ceid[k];
    const float alpha = g_eexp[(size_t)eid * 4 + hd] * invden;
    const float4 hv = *reinterpret_cast<const float4*>(&h[(size_t)src * 256 + c]);
    acc.x = fmaf(alpha, hv.x, acc.x);
    acc.y = fmaf(alpha, hv.y, acc.y);
    acc.z = fmaf(alpha, hv.z, acc.z);
    acc.w = fmaf(alpha, hv.w, acc.w);
  }
  const float4 bi = *reinterpret_cast<const float4*>(&bias[c]);
  const float4 ga = *reinterpret_cast<const float4*>(&gamma[c]);
  const float4 be = *reinterpret_cast<const float4*>(&beta[c]);
  const float4 me = *reinterpret_cast<const float4*>(&mean[c]);
  const float4 va = *reinterpret_cast<const float4*>(&var[c]);
  float4 o;
  o.x = fmaxf((acc.x + bi.x - me.x) * rsqrtf(va.x + 1e-5f) * ga.x + be.x, 0.f);
  o.y = fmaxf((acc.y + bi.y - me.y) * rsqrtf(va.y + 1e-5f) * ga.y + be.y, 0.f);
  o.z = fmaxf((acc.z + bi.z - me.z) * rsqrtf(va.z + 1e-5f) * ga.z + be.z, 0.f);
  o.w = fmaxf((acc.w + bi.w - me.w) * rsqrtf(va.w + 1e-5f) * ga.w + be.w, 0.f);
  *reinterpret_cast<float4*>(&out[(size_t)node * 256 + c]) = o;
}

// Layer 3: F=16 (H=1). 16 nodes per block, 16 channels each.
__global__ __launch_bounds__(256) void k_agg16(
    const float* __restrict__ h, const float* __restrict__ bias,
    float* __restrict__ out, int n) {
  const int local = threadIdx.x >> 4;
  const int c = threadIdx.x & 15;
  const int node = blockIdx.x * 16 + local;
  if (node >= n) return;
  const float invden = 1.f / g_den[node];
  const int k0 = g_off[node];
  const int k1 = g_off[node + 1];
  float acc = 0.f;
  for (int k = k0; k < k1; k++) {
    const int src = g_csrc[k];
    const int eid = g_ceid[k];
    acc = fmaf(g_eexp[eid] * invden, h[(size_t)src * 16 + c], acc);
  }
  out[(size_t)node * 16 + c] = acc + bias[c];
}

// ---------------- host ----------------
extern "C" void kernel_launch(void* const* d_in, const int* in_sizes, int n_in,
                              void* d_out, int out_size) {
  const float* x   = (const float*)d_in[0];
  const int*   ei  = (const int*)d_in[1];       // int32 (JAX x64 disabled)
  const float* W1  = (const float*)d_in[2];
  const float* as1 = (const float*)d_in[3];
  const float* ad1 = (const float*)d_in[4];
  const float* b1  = (const float*)d_in[5];
  const float* g1  = (const float*)d_in[6];
  const float* be1 = (const float*)d_in[7];
  const float* m1  = (const float*)d_in[8];
  const float* v1  = (const float*)d_in[9];
  const float* W2  = (const float*)d_in[10];
  const float* as2 = (const float*)d_in[11];
  const float* ad2 = (const float*)d_in[12];
  const float* b2  = (const float*)d_in[13];
  const float* g2  = (const float*)d_in[14];
  const float* be2 = (const float*)d_in[15];
  const float* m2  = (const float*)d_in[16];
  const float* v2  = (const float*)d_in[17];
  const float* W3  = (const float*)d_in[18];
  const float* as3 = (const float*)d_in[19];
  const float* ad3 = (const float*)d_in[20];
  const float* b3  = (const float*)d_in[21];

  const int n  = in_sizes[0] / 128;    // 50000
  const int E  = in_sizes[1] / 2;      // 800000
  const int ET = E + n;

  float* p_h;   cudaGetSymbolAddress((void**)&p_h,   g_h);
  float* p_out; cudaGetSymbolAddress((void**)&p_out, g_out);

  const int TB = 256;
  const int edgeBlocks = (ET + TB - 1) / TB;

  // ---- CSR by dst (shared by all 3 layers) ----
  k_zero_deg<<<(n + TB - 1) / TB, TB>>>(n);
  k_count<<<edgeBlocks, TB>>>(ei, E, n);
  k_scan<<<1, 1024>>>(n);
  k_scatter<<<edgeBlocks, TB>>>(ei, E, n);

  // ---- layer 1: GAT(128 -> 64x4) + BN + ReLU ----
  {
    dim3 grid(2, (n + 127) / 128);
    gemm_k<<<grid, 256>>>(x, W1, p_h, n, 256, 128);
    k_zero_den<<<(n * 4 + TB - 1) / TB, TB>>>(n * 4);
    k_node_attn<<<(n * 4 * 32 + TB - 1) / TB, TB>>>(p_h, as1, ad1, n, 4, 64);
    k_edge4<<<edgeBlocks, TB>>>(ei, E, n);
    k_agg256<<<(n + 3) / 4, 256>>>(p_h, b1, g1, be1, m1, v1, p_out, n);
  }

  // ---- layer 2: GAT(256 -> 64x4) + BN + ReLU ----
  {
    dim3 grid(2, (n + 127) / 128);
    gemm_k<<<grid, 256>>>(p_out, W2, p_h, n, 256, 256);
    k_zero_den<<<(n * 4 + TB - 1) / TB, TB>>>(n * 4);
    k_node_attn<<<(n * 4 * 32 + TB - 1) / TB, TB>>>(p_h, as2, ad2, n, 4, 64);
    k_edge4<<<edgeBlocks, TB>>>(ei, E, n);
    k_agg256<<<(n + 3) / 4, 256>>>(p_h, b2, g2, be2, m2, v2, p_out, n);
  }

  // ---- layer 3: GAT(256 -> 16, single head, no concat) ----
  {
    gemm_n16<<<((size_t)n * 16 + TB - 1) / TB, TB>>>(p_out, W3, p_h, n);
    k_zero_den<<<(n + TB - 1) / TB, TB>>>(n);
    k_node_attn<<<(n * 32 + TB - 1) / TB, TB>>>(p_h, as3, ad3, n, 1, 16);
    k_edge1<<<edgeBlocks, TB>>>(ei, E, n);
    k_agg16<<<(n + 15) / 16, 256>>>(p_h, b3, (float*)d_out, n);
  }
}

// round 4
// speedup vs baseline: 1.8662x; 1.2280x over previous
#include <cuda_runtime.h>
#include <math.h>

#define NNODES 50000
#define NEDGES 800000
#define ETMAX (NEDGES + NNODES)

// ---------------- scratch (device globals; no allocation allowed) ----------
__device__ __align__(16) float g_h[(size_t)NNODES * 256];   // post-GEMM features
__device__ __align__(16) float g_out[(size_t)NNODES * 256]; // aggregated output / next input
__device__ __align__(16) float g_s[NNODES * 4];             // per (node,head) src score
__device__ __align__(16) float g_d[NNODES * 4];             // per (node,head) dst score
__device__ __align__(16) float g_den[NNODES * 4];           // segment sum of exp
__device__ __align__(16) float g_eexp[(size_t)ETMAX * 4];   // exp(score), CSR order
__device__ int   g_deg[NNODES];
__device__ int   g_off[NNODES + 1];
__device__ int   g_cur[NNODES];
__device__ int   g_csrc[ETMAX];                  // CSR-by-dst: source node
__device__ int   g_epos[ETMAX];                  // edge id -> CSR position

// ---------------- f32x2 helpers ----------------
#define PACK2(dst, x) asm("mov.b64 %0, {%1, %1};" : "=l"(dst) : "f"(x))
#define FMA2(acc, ai, bb) asm("fma.rn.f32x2 %0, %1, %2, %0;" : "+l"(acc) : "l"(ai), "l"(bb))
#define UNPK2(lo, hi, p) asm("mov.b64 {%0, %1}, %2;" : "=f"(lo), "=f"(hi) : "l"(p))

// ---------------- GEMM (N=256 fixed): C = A@B, fused attn dots -------------
// Also computes g_s[row*4+head] = <C[row, head*64..], asrc[head]>, same for d.
__global__ __launch_bounds__(256) void gemm256_fused(
    const float* __restrict__ A, const float* __restrict__ B, float* __restrict__ C,
    const float* __restrict__ asrc, const float* __restrict__ adst,
    int M, int K) {
  const int N = 256;
  __shared__ __align__(16) float As[16][128];
  __shared__ __align__(16) float Bs[16][128];
  const int tid = threadIdx.x;
  const int tx = tid & 15;
  const int ty = tid >> 4;
  const int rowBase = blockIdx.y * 128;
  const int colBase = blockIdx.x * 128;

  const int ar  = tid >> 1;
  const int akq = (tid & 1) * 8;
  const int bkr = tid >> 5;
  const int bnc = (tid & 31) * 4;

  unsigned long long accp[8][4];
#pragma unroll
  for (int i = 0; i < 8; i++)
#pragma unroll
    for (int j = 0; j < 4; j++) accp[i][j] = 0ull;

  const bool aok = (rowBase + ar) < M;
  const float* Aptr = A + (size_t)(rowBase + ar) * K + akq;
  const float* Bptr = B + (size_t)bkr * N + colBase + bnc;

  float4 a0 = make_float4(0,0,0,0), a1 = a0, b0, b1;
  if (aok) {
    a0 = *reinterpret_cast<const float4*>(Aptr + 0);
    a1 = *reinterpret_cast<const float4*>(Aptr + 4);
  }
  b0 = *reinterpret_cast<const float4*>(Bptr);
  b1 = *reinterpret_cast<const float4*>(Bptr + (size_t)8 * N);

  const int T = K / 16;
  for (int t = 0; t < T; t++) {
    As[akq + 0][ar] = a0.x; As[akq + 1][ar] = a0.y;
    As[akq + 2][ar] = a0.z; As[akq + 3][ar] = a0.w;
    As[akq + 4][ar] = a1.x; As[akq + 5][ar] = a1.y;
    As[akq + 6][ar] = a1.z; As[akq + 7][ar] = a1.w;
    *reinterpret_cast<float4*>(&Bs[bkr][bnc]) = b0;
    *reinterpret_cast<float4*>(&Bs[bkr + 8][bnc]) = b1;
    __syncthreads();

    if (t + 1 < T) {
      const float* Ap = Aptr + (t + 1) * 16;
      if (aok) {
        a0 = *reinterpret_cast<const float4*>(Ap + 0);
        a1 = *reinterpret_cast<const float4*>(Ap + 4);
      }
      const float* Bp = Bptr + (size_t)(t + 1) * 16 * N;
      b0 = *reinterpret_cast<const float4*>(Bp);
      b1 = *reinterpret_cast<const float4*>(Bp + (size_t)8 * N);
    }

#pragma unroll
    for (int kk = 0; kk < 16; kk++) {
      const float4 af0 = *reinterpret_cast<const float4*>(&As[kk][ty * 8]);
      const float4 af1 = *reinterpret_cast<const float4*>(&As[kk][ty * 8 + 4]);
      const ulonglong2 bq0 = *reinterpret_cast<const ulonglong2*>(&Bs[kk][tx * 8]);
      const ulonglong2 bq1 = *reinterpret_cast<const ulonglong2*>(&Bs[kk][tx * 8 + 4]);
      float a[8] = {af0.x, af0.y, af0.z, af0.w, af1.x, af1.y, af1.z, af1.w};
#pragma unroll
      for (int i = 0; i < 8; i++) {
        unsigned long long ai;
        PACK2(ai, a[i]);
        FMA2(accp[i][0], ai, bq0.x);
        FMA2(accp[i][1], ai, bq0.y);
        FMA2(accp[i][2], ai, bq1.x);
        FMA2(accp[i][3], ai, bq1.y);
      }
    }
    __syncthreads();
  }

  // unpack
  float accf[8][8];
#pragma unroll
  for (int i = 0; i < 8; i++)
#pragma unroll
    for (int j = 0; j < 4; j++) UNPK2(accf[i][2 * j], accf[i][2 * j + 1], accp[i][j]);

  // attention vectors for this thread's 8 columns
  const int c0 = colBase + tx * 8;        // global col
  const int head = c0 >> 6;
  float asv[8], adv[8];
#pragma unroll
  for (int j = 0; j < 8; j++) { asv[j] = asrc[c0 + j]; adv[j] = adst[c0 + j]; }

#pragma unroll
  for (int i = 0; i < 8; i++) {
    const int row = rowBase + ty * 8 + i;
    float sd = 0.f, dd = 0.f;
#pragma unroll
    for (int j = 0; j < 8; j++) {
      sd = fmaf(accf[i][j], asv[j], sd);
      dd = fmaf(accf[i][j], adv[j], dd);
    }
#pragma unroll
    for (int o = 1; o < 8; o <<= 1) {
      sd += __shfl_xor_sync(0xffffffffu, sd, o);
      dd += __shfl_xor_sync(0xffffffffu, dd, o);
    }
    if (row < M) {
      if ((tx & 7) == 0) { g_s[row * 4 + head] = sd; g_d[row * 4 + head] = dd; }
      float4* cp = reinterpret_cast<float4*>(&C[(size_t)row * N + c0]);
      cp[0] = make_float4(accf[i][0], accf[i][1], accf[i][2], accf[i][3]);
      cp[1] = make_float4(accf[i][4], accf[i][5], accf[i][6], accf[i][7]);
    }
  }
}

// ---------------- GEMM layer 3: N=16, K=256, fused attn --------------------
__global__ __launch_bounds__(256) void gemm_n16_fused(
    const float* __restrict__ A, const float* __restrict__ B, float* __restrict__ C,
    const float* __restrict__ as3, const float* __restrict__ ad3, int M) {
  const int t = blockIdx.x * blockDim.x + threadIdx.x;
  const int row = t >> 4;
  const int nc = t & 15;
  if (row >= M) return;
  const float* a = A + (size_t)row * 256;
  float acc = 0.f;
#pragma unroll 8
  for (int k = 0; k < 256; k += 4) {
    const float4 av = *reinterpret_cast<const float4*>(a + k);
    acc = fmaf(av.x, B[(k + 0) * 16 + nc], acc);
    acc = fmaf(av.y, B[(k + 1) * 16 + nc], acc);
    acc = fmaf(av.z, B[(k + 2) * 16 + nc], acc);
    acc = fmaf(av.w, B[(k + 3) * 16 + nc], acc);
  }
  C[(size_t)row * 16 + nc] = acc;
  float sv = acc * as3[nc];
  float dv = acc * ad3[nc];
#pragma unroll
  for (int o = 1; o < 16; o <<= 1) {
    sv += __shfl_xor_sync(0xffffffffu, sv, o);
    dv += __shfl_xor_sync(0xffffffffu, dv, o);
  }
  if (nc == 0) { g_s[row] = sv; g_d[row] = dv; }
}

// ---------------- CSR build --------------------------------------------------
__global__ void k_zero_deg(int n) {
  int i = blockIdx.x * blockDim.x + threadIdx.x;
  if (i < n) g_deg[i] = 0;
}

__global__ void k_count(const int* __restrict__ ei, int E, int n) {
  int e = blockIdx.x * blockDim.x + threadIdx.x;
  if (e >= E + n) return;
  int dst = (e < E) ? ei[E + e] : (e - E);
  atomicAdd(&g_deg[dst], 1);
}

__global__ void k_scan(int n) {   // 1024 threads, shuffle scan
  __shared__ int wsum[32];
  __shared__ int wexcl[32];
  __shared__ int carry, total;
  const int tid = threadIdx.x;
  const int lane = tid & 31;
  const int wid = tid >> 5;
  if (tid == 0) carry = 0;
  __syncthreads();
  for (int base = 0; base < n; base += 1024) {
    const int i = base + tid;
    const int v = (i < n) ? g_deg[i] : 0;
    int s = v;
#pragma unroll
    for (int o = 1; o < 32; o <<= 1) {
      int tt = __shfl_up_sync(0xffffffffu, s, o);
      if (lane >= o) s += tt;
    }
    if (lane == 31) wsum[wid] = s;
    __syncthreads();
    if (wid == 0) {
      int w = wsum[lane];
      int ws = w;
#pragma unroll
      for (int o = 1; o < 32; o <<= 1) {
        int tt = __shfl_up_sync(0xffffffffu, ws, o);
        if (lane >= o) ws += tt;
      }
      wexcl[lane] = ws - w;
      if (lane == 31) total = ws;
    }
    __syncthreads();
    const int excl = carry + wexcl[wid] + (s - v);
    if (i < n) { g_off[i] = excl; g_cur[i] = excl; }
    __syncthreads();
    if (tid == 0) carry += total;
    __syncthreads();
  }
  if (tid == 0) g_off[n] = carry;
}

__global__ void k_scatter(const int* __restrict__ ei, int E, int n) {
  int e = blockIdx.x * blockDim.x + threadIdx.x;
  if (e >= E + n) return;
  int src, dst;
  if (e < E) { src = ei[e]; dst = ei[E + e]; }
  else       { src = dst = e - E; }
  const int pos = atomicAdd(&g_cur[dst], 1);
  g_csrc[pos] = src;
  g_epos[e] = pos;
}

// ---------------- attention edge passes ----------------
__global__ void k_zero_den(int cnt) {
  int i = blockIdx.x * blockDim.x + threadIdx.x;
  if (i < cnt) g_den[i] = 0.f;
}

// H=4: score -> leakyrelu -> exp (unshifted; scores O(1)) -> CSR-order store.
__global__ void k_edge4(const int* __restrict__ ei, int E, int n) {
  const int e = blockIdx.x * blockDim.x + threadIdx.x;
  const int ET = E + n;
  if (e >= ET) return;
  int src, dst;
  if (e < E) { src = ei[e]; dst = ei[E + e]; }
  else       { src = dst = e - E; }
  const float4 s = *reinterpret_cast<const float4*>(&g_s[src * 4]);
  const float4 d = *reinterpret_cast<const float4*>(&g_d[dst * 4]);
  float v0 = s.x + d.x, v1 = s.y + d.y, v2 = s.z + d.z, v3 = s.w + d.w;
  v0 = (v0 > 0.f) ? v0 : 0.2f * v0;
  v1 = (v1 > 0.f) ? v1 : 0.2f * v1;
  v2 = (v2 > 0.f) ? v2 : 0.2f * v2;
  v3 = (v3 > 0.f) ? v3 : 0.2f * v3;
  const float e0 = __expf(v0), e1 = __expf(v1), e2 = __expf(v2), e3 = __expf(v3);
  const int pos = g_epos[e];
  *reinterpret_cast<float4*>(&g_eexp[(size_t)pos * 4]) = make_float4(e0, e1, e2, e3);
  atomicAdd(&g_den[dst * 4 + 0], e0);
  atomicAdd(&g_den[dst * 4 + 1], e1);
  atomicAdd(&g_den[dst * 4 + 2], e2);
  atomicAdd(&g_den[dst * 4 + 3], e3);
}

// H=1
__global__ void k_edge1(const int* __restrict__ ei, int E, int n) {
  const int e = blockIdx.x * blockDim.x + threadIdx.x;
  const int ET = E + n;
  if (e >= ET) return;
  int src, dst;
  if (e < E) { src = ei[e]; dst = ei[E + e]; }
  else       { src = dst = e - E; }
  float v = g_s[src] + g_d[dst];
  v = (v > 0.f) ? v : 0.2f * v;
  const float ex = __expf(v);
  g_eexp[g_epos[e]] = ex;
  atomicAdd(&g_den[dst], ex);
}

// ---------------- aggregation ----------------
// F=256: 64 threads/node (float4), 4 nodes/block. Normalize at end. Fused BN+ReLU.
__global__ __launch_bounds__(256) void k_agg256(
    const float* __restrict__ h,
    const float* __restrict__ bias, const float* __restrict__ gamma,
    const float* __restrict__ beta, const float* __restrict__ mean,
    const float* __restrict__ var, float* __restrict__ out, int n) {
  const int grp = threadIdx.x >> 6;
  const int c4  = threadIdx.x & 63;
  const int node = blockIdx.x * 4 + grp;
  if (node >= n) return;
  const int c = c4 * 4;
  const int hd = c >> 6;
  const int k0 = g_off[node];
  const int k1 = g_off[node + 1];
  float4 acc = make_float4(0.f, 0.f, 0.f, 0.f);
  int k = k0;
  int src_n = (k < k1) ? g_csrc[k] : 0;
  float al_n  = (k < k1) ? g_eexp[(size_t)k * 4 + hd] : 0.f;
  while (k < k1) {
    const int src = src_n;
    const float al = al_n;
    const float4 hv = *reinterpret_cast<const float4*>(&h[(size_t)src * 256 + c]);
    k++;
    if (k < k1) {
      src_n = g_csrc[k];
      al_n  = g_eexp[(size_t)k * 4 + hd];
    }
    acc.x = fmaf(al, hv.x, acc.x);
    acc.y = fmaf(al, hv.y, acc.y);
    acc.z = fmaf(al, hv.z, acc.z);
    acc.w = fmaf(al, hv.w, acc.w);
  }
  const float invden = 1.f / g_den[node * 4 + hd];
  acc.x *= invden; acc.y *= invden; acc.z *= invden; acc.w *= invden;
  const float4 bi = *reinterpret_cast<const float4*>(&bias[c]);
  const float4 ga = *reinterpret_cast<const float4*>(&gamma[c]);
  const float4 be = *reinterpret_cast<const float4*>(&beta[c]);
  const float4 me = *reinterpret_cast<const float4*>(&mean[c]);
  const float4 va = *reinterpret_cast<const float4*>(&var[c]);
  float4 o;
  o.x = fmaxf((acc.x + bi.x - me.x) * rsqrtf(va.x + 1e-5f) * ga.x + be.x, 0.f);
  o.y = fmaxf((acc.y + bi.y - me.y) * rsqrtf(va.y + 1e-5f) * ga.y + be.y, 0.f);
  o.z = fmaxf((acc.z + bi.z - me.z) * rsqrtf(va.z + 1e-5f) * ga.z + be.z, 0.f);
  o.w = fmaxf((acc.w + bi.w - me.w) * rsqrtf(va.w + 1e-5f) * ga.w + be.w, 0.f);
  *reinterpret_cast<float4*>(&out[(size_t)node * 256 + c]) = o;
}

// F=16 (H=1): 16 nodes per block, 16 channels each.
__global__ __launch_bounds__(256) void k_agg16(
    const float* __restrict__ h, const float* __restrict__ bias,
    float* __restrict__ out, int n) {
  const int local = threadIdx.x >> 4;
  const int c = threadIdx.x & 15;
  const int node = blockIdx.x * 16 + local;
  if (node >= n) return;
  const int k0 = g_off[node];
  const int k1 = g_off[node + 1];
  float acc = 0.f;
  for (int k = k0; k < k1; k++) {
    const int src = g_csrc[k];
    acc = fmaf(g_eexp[k], h[(size_t)src * 16 + c], acc);
  }
  out[(size_t)node * 16 + c] = acc / g_den[node] + bias[c];
}

// ---------------- host ----------------
extern "C" void kernel_launch(void* const* d_in, const int* in_sizes, int n_in,
                              void* d_out, int out_size) {
  const float* x   = (const float*)d_in[0];
  const int*   ei  = (const int*)d_in[1];       // int32 (JAX x64 disabled)
  const float* W1  = (const float*)d_in[2];
  const float* as1 = (const float*)d_in[3];
  const float* ad1 = (const float*)d_in[4];
  const float* b1  = (const float*)d_in[5];
  const float* g1  = (const float*)d_in[6];
  const float* be1 = (const float*)d_in[7];
  const float* m1  = (const float*)d_in[8];
  const float* v1  = (const float*)d_in[9];
  const float* W2  = (const float*)d_in[10];
  const float* as2 = (const float*)d_in[11];
  const float* ad2 = (const float*)d_in[12];
  const float* b2  = (const float*)d_in[13];
  const float* g2  = (const float*)d_in[14];
  const float* be2 = (const float*)d_in[15];
  const float* m2  = (const float*)d_in[16];
  const float* v2  = (const float*)d_in[17];
  const float* W3  = (const float*)d_in[18];
  const float* as3 = (const float*)d_in[19];
  const float* ad3 = (const float*)d_in[20];
  const float* b3  = (const float*)d_in[21];

  const int n  = in_sizes[0] / 128;    // 50000
  const int E  = in_sizes[1] / 2;      // 800000
  const int ET = E + n;

  float* p_h;   cudaGetSymbolAddress((void**)&p_h,   g_h);
  float* p_out; cudaGetSymbolAddress((void**)&p_out, g_out);

  const int TB = 256;
  const int edgeBlocks = (ET + TB - 1) / TB;

  // ---- CSR by dst (shared by all 3 layers) ----
  k_zero_deg<<<(n + TB - 1) / TB, TB>>>(n);
  k_count<<<edgeBlocks, TB>>>(ei, E, n);
  k_scan<<<1, 1024>>>(n);
  k_scatter<<<edgeBlocks, TB>>>(ei, E, n);

  // ---- layer 1: GAT(128 -> 64x4) + BN + ReLU ----
  {
    dim3 grid(2, (n + 127) / 128);
    gemm256_fused<<<grid, 256>>>(x, W1, p_h, as1, ad1, n, 128);
    k_zero_den<<<(n * 4 + TB - 1) / TB, TB>>>(n * 4);
    k_edge4<<<edgeBlocks, TB>>>(ei, E, n);
    k_agg256<<<(n + 3) / 4, 256>>>(p_h, b1, g1, be1, m1, v1, p_out, n);
  }

  // ---- layer 2: GAT(256 -> 64x4) + BN + ReLU ----
  {
    dim3 grid(2, (n + 127) / 128);
    gemm256_fused<<<grid, 256>>>(p_out, W2, p_h, as2, ad2, n, 256);
    k_zero_den<<<(n * 4 + TB - 1) / TB, TB>>>(n * 4);
    k_edge4<<<edgeBlocks, TB>>>(ei, E, n);
    k_agg256<<<(n + 3) / 4, 256>>>(p_h, b2, g2, be2, m2, v2, p_out, n);
  }

  // ---- layer 3: GAT(256 -> 16, single head, no concat) ----
  {
    gemm_n16_fused<<<((size_t)n * 16 + TB - 1) / TB, TB>>>(p_out, W3, p_h, as3, ad3, n);
    k_zero_den<<<(n + TB - 1) / TB, TB>>>(n);
    k_edge1<<<edgeBlocks, TB>>>(ei, E, n);
    k_agg16<<<(n + 15) / 16, 256>>>(p_h, b3, (float*)d_out, n);
  }
}

// round 5
// speedup vs baseline: 2.1012x; 1.1260x over previous
#include <cuda_runtime.h>
#include <math.h>

#define NNODES 50000
#define NEDGES 800000
#define ETMAX (NEDGES + NNODES)

// ---------------- scratch (device globals; no allocation allowed) ----------
__device__ __align__(16) float g_h[(size_t)NNODES * 256];   // post-GEMM features
__device__ __align__(16) float g_out[(size_t)NNODES * 256]; // aggregated output / next input
__device__ __align__(16) float g_s[NNODES * 4];             // per (node,head) src score
__device__ __align__(16) float g_d[NNODES * 4];             // per (node,head) dst score
__device__ int   g_deg[NNODES];
__device__ int   g_off[NNODES + 1];
__device__ int   g_cur[NNODES];
__device__ int   g_csrc[ETMAX];                  // CSR-by-dst: source node

// ---------------- f32x2 helpers ----------------
#define PACK2(dst, x) asm("mov.b64 %0, {%1, %1};" : "=l"(dst) : "f"(x))
#define FMA2(acc, ai, bb) asm("fma.rn.f32x2 %0, %1, %2, %0;" : "+l"(acc) : "l"(ai), "l"(bb))
#define UNPK2(lo, hi, p) asm("mov.b64 {%0, %1}, %2;" : "=f"(lo), "=f"(hi) : "l"(p))

// ---------------- GEMM (N=256 fixed): C = A@B, fused attn dots -------------
// Also computes g_s[row*4+head] = <C[row, head*64..], asrc[head]>, same for d.
__global__ __launch_bounds__(256) void gemm256_fused(
    const float* __restrict__ A, const float* __restrict__ B, float* __restrict__ C,
    const float* __restrict__ asrc, const float* __restrict__ adst,
    int M, int K) {
  const int N = 256;
  __shared__ __align__(16) float As[16][128];
  __shared__ __align__(16) float Bs[16][128];
  const int tid = threadIdx.x;
  const int tx = tid & 15;
  const int ty = tid >> 4;
  const int rowBase = blockIdx.y * 128;
  const int colBase = blockIdx.x * 128;

  const int ar  = tid >> 1;
  const int akq = (tid & 1) * 8;
  const int bkr = tid >> 5;
  const int bnc = (tid & 31) * 4;

  unsigned long long accp[8][4];
#pragma unroll
  for (int i = 0; i < 8; i++)
#pragma unroll
    for (int j = 0; j < 4; j++) accp[i][j] = 0ull;

  const bool aok = (rowBase + ar) < M;
  const float* Aptr = A + (size_t)(rowBase + ar) * K + akq;
  const float* Bptr = B + (size_t)bkr * N + colBase + bnc;

  float4 a0 = make_float4(0,0,0,0), a1 = a0, b0, b1;
  if (aok) {
    a0 = *reinterpret_cast<const float4*>(Aptr + 0);
    a1 = *reinterpret_cast<const float4*>(Aptr + 4);
  }
  b0 = *reinterpret_cast<const float4*>(Bptr);
  b1 = *reinterpret_cast<const float4*>(Bptr + (size_t)8 * N);

  const int T = K / 16;
  for (int t = 0; t < T; t++) {
    As[akq + 0][ar] = a0.x; As[akq + 1][ar] = a0.y;
    As[akq + 2][ar] = a0.z; As[akq + 3][ar] = a0.w;
    As[akq + 4][ar] = a1.x; As[akq + 5][ar] = a1.y;
    As[akq + 6][ar] = a1.z; As[akq + 7][ar] = a1.w;
    *reinterpret_cast<float4*>(&Bs[bkr][bnc]) = b0;
    *reinterpret_cast<float4*>(&Bs[bkr + 8][bnc]) = b1;
    __syncthreads();

    if (t + 1 < T) {
      const float* Ap = Aptr + (t + 1) * 16;
      if (aok) {
        a0 = *reinterpret_cast<const float4*>(Ap + 0);
        a1 = *reinterpret_cast<const float4*>(Ap + 4);
      }
      const float* Bp = Bptr + (size_t)(t + 1) * 16 * N;
      b0 = *reinterpret_cast<const float4*>(Bp);
      b1 = *reinterpret_cast<const float4*>(Bp + (size_t)8 * N);
    }

#pragma unroll
    for (int kk = 0; kk < 16; kk++) {
      const float4 af0 = *reinterpret_cast<const float4*>(&As[kk][ty * 8]);
      const float4 af1 = *reinterpret_cast<const float4*>(&As[kk][ty * 8 + 4]);
      const ulonglong2 bq0 = *reinterpret_cast<const ulonglong2*>(&Bs[kk][tx * 8]);
      const ulonglong2 bq1 = *reinterpret_cast<const ulonglong2*>(&Bs[kk][tx * 8 + 4]);
      float a[8] = {af0.x, af0.y, af0.z, af0.w, af1.x, af1.y, af1.z, af1.w};
#pragma unroll
      for (int i = 0; i < 8; i++) {
        unsigned long long ai;
        PACK2(ai, a[i]);
        FMA2(accp[i][0], ai, bq0.x);
        FMA2(accp[i][1], ai, bq0.y);
        FMA2(accp[i][2], ai, bq1.x);
        FMA2(accp[i][3], ai, bq1.y);
      }
    }
    __syncthreads();
  }

  float accf[8][8];
#pragma unroll
  for (int i = 0; i < 8; i++)
#pragma unroll
    for (int j = 0; j < 4; j++) UNPK2(accf[i][2 * j], accf[i][2 * j + 1], accp[i][j]);

  const int c0 = colBase + tx * 8;
  const int head = c0 >> 6;
  float asv[8], adv[8];
#pragma unroll
  for (int j = 0; j < 8; j++) { asv[j] = asrc[c0 + j]; adv[j] = adst[c0 + j]; }

#pragma unroll
  for (int i = 0; i < 8; i++) {
    const int row = rowBase + ty * 8 + i;
    float sd = 0.f, dd = 0.f;
#pragma unroll
    for (int j = 0; j < 8; j++) {
      sd = fmaf(accf[i][j], asv[j], sd);
      dd = fmaf(accf[i][j], adv[j], dd);
    }
#pragma unroll
    for (int o = 1; o < 8; o <<= 1) {
      sd += __shfl_xor_sync(0xffffffffu, sd, o);
      dd += __shfl_xor_sync(0xffffffffu, dd, o);
    }
    if (row < M) {
      if ((tx & 7) == 0) { g_s[row * 4 + head] = sd; g_d[row * 4 + head] = dd; }
      float4* cp = reinterpret_cast<float4*>(&C[(size_t)row * N + c0]);
      cp[0] = make_float4(accf[i][0], accf[i][1], accf[i][2], accf[i][3]);
      cp[1] = make_float4(accf[i][4], accf[i][5], accf[i][6], accf[i][7]);
    }
  }
}

// ---------------- GEMM layer 3: N=16, K=256, fused attn --------------------
__global__ __launch_bounds__(256) void gemm_n16_fused(
    const float* __restrict__ A, const float* __restrict__ B, float* __restrict__ C,
    const float* __restrict__ as3, const float* __restrict__ ad3, int M) {
  const int t = blockIdx.x * blockDim.x + threadIdx.x;
  const int row = t >> 4;
  const int nc = t & 15;
  if (row >= M) return;
  const float* a = A + (size_t)row * 256;
  float acc = 0.f;
#pragma unroll 8
  for (int k = 0; k < 256; k += 4) {
    const float4 av = *reinterpret_cast<const float4*>(a + k);
    acc = fmaf(av.x, B[(k + 0) * 16 + nc], acc);
    acc = fmaf(av.y, B[(k + 1) * 16 + nc], acc);
    acc = fmaf(av.z, B[(k + 2) * 16 + nc], acc);
    acc = fmaf(av.w, B[(k + 3) * 16 + nc], acc);
  }
  C[(size_t)row * 16 + nc] = acc;
  float sv = acc * as3[nc];
  float dv = acc * ad3[nc];
#pragma unroll
  for (int o = 1; o < 16; o <<= 1) {
    sv += __shfl_xor_sync(0xffffffffu, sv, o);
    dv += __shfl_xor_sync(0xffffffffu, dv, o);
  }
  if (nc == 0) { g_s[row] = sv; g_d[row] = dv; }
}

// ---------------- CSR build --------------------------------------------------
__global__ void k_zero_deg(int n) {
  int i = blockIdx.x * blockDim.x + threadIdx.x;
  if (i < n) g_deg[i] = 0;
}

__global__ void k_count(const int* __restrict__ ei, int E, int n) {
  int e = blockIdx.x * blockDim.x + threadIdx.x;
  if (e >= E + n) return;
  int dst = (e < E) ? ei[E + e] : (e - E);
  atomicAdd(&g_deg[dst], 1);
}

__global__ void k_scan(int n) {   // 1024 threads, shuffle scan
  __shared__ int wsum[32];
  __shared__ int wexcl[32];
  __shared__ int carry, total;
  const int tid = threadIdx.x;
  const int lane = tid & 31;
  const int wid = tid >> 5;
  if (tid == 0) carry = 0;
  __syncthreads();
  for (int base = 0; base < n; base += 1024) {
    const int i = base + tid;
    const int v = (i < n) ? g_deg[i] : 0;
    int s = v;
#pragma unroll
    for (int o = 1; o < 32; o <<= 1) {
      int tt = __shfl_up_sync(0xffffffffu, s, o);
      if (lane >= o) s += tt;
    }
    if (lane == 31) wsum[wid] = s;
    __syncthreads();
    if (wid == 0) {
      int w = wsum[lane];
      int ws = w;
#pragma unroll
      for (int o = 1; o < 32; o <<= 1) {
        int tt = __shfl_up_sync(0xffffffffu, ws, o);
        if (lane >= o) ws += tt;
      }
      wexcl[lane] = ws - w;
      if (lane == 31) total = ws;
    }
    __syncthreads();
    const int excl = carry + wexcl[wid] + (s - v);
    if (i < n) { g_off[i] = excl; g_cur[i] = excl; }
    __syncthreads();
    if (tid == 0) carry += total;
    __syncthreads();
  }
  if (tid == 0) g_off[n] = carry;
}

__global__ void k_scatter(const int* __restrict__ ei, int E, int n) {
  int e = blockIdx.x * blockDim.x + threadIdx.x;
  if (e >= E + n) return;
  int src, dst;
  if (e < E) { src = ei[e]; dst = ei[E + e]; }
  else       { src = dst = e - E; }
  const int pos = atomicAdd(&g_cur[dst], 1);
  g_csrc[pos] = src;
}

// ---------------- fully fused aggregation -----------------------------------
// F=256: 64 threads/node (float4 channels), 4 nodes/block.
// Per edge: softmax weight computed in-register from g_s/g_d (no edge pass,
// no atomics). Normalize at end, then bias+BN+ReLU.
__global__ __launch_bounds__(256) void k_agg256(
    const float* __restrict__ h,
    const float* __restrict__ bias, const float* __restrict__ gamma,
    const float* __restrict__ beta, const float* __restrict__ mean,
    const float* __restrict__ var, float* __restrict__ out, int n) {
  const int grp = threadIdx.x >> 6;
  const int c4  = threadIdx.x & 63;
  const int node = blockIdx.x * 4 + grp;
  if (node >= n) return;
  const int c = c4 * 4;
  const int hd = c >> 6;
  const float dscore = g_d[node * 4 + hd];
  const int k0 = g_off[node];
  const int k1 = g_off[node + 1];
  float4 acc = make_float4(0.f, 0.f, 0.f, 0.f);
  float den = 0.f;
  int k = k0;
  int src_n = (k < k1) ? g_csrc[k] : 0;
  while (k < k1) {
    const int src = src_n;
    float v = g_s[src * 4 + hd] + dscore;
    const float4 hv = *reinterpret_cast<const float4*>(&h[(size_t)src * 256 + c]);
    k++;
    if (k < k1) src_n = g_csrc[k];
    v = (v > 0.f) ? v : 0.2f * v;       // leaky relu
    const float al = __expf(v);         // unshifted exp: scores are O(1)
    den += al;
    acc.x = fmaf(al, hv.x, acc.x);
    acc.y = fmaf(al, hv.y, acc.y);
    acc.z = fmaf(al, hv.z, acc.z);
    acc.w = fmaf(al, hv.w, acc.w);
  }
  const float invden = 1.f / den;
  acc.x *= invden; acc.y *= invden; acc.z *= invden; acc.w *= invden;
  const float4 bi = *reinterpret_cast<const float4*>(&bias[c]);
  const float4 ga = *reinterpret_cast<const float4*>(&gamma[c]);
  const float4 be = *reinterpret_cast<const float4*>(&beta[c]);
  const float4 me = *reinterpret_cast<const float4*>(&mean[c]);
  const float4 va = *reinterpret_cast<const float4*>(&var[c]);
  float4 o;
  o.x = fmaxf((acc.x + bi.x - me.x) * rsqrtf(va.x + 1e-5f) * ga.x + be.x, 0.f);
  o.y = fmaxf((acc.y + bi.y - me.y) * rsqrtf(va.y + 1e-5f) * ga.y + be.y, 0.f);
  o.z = fmaxf((acc.z + bi.z - me.z) * rsqrtf(va.z + 1e-5f) * ga.z + be.z, 0.f);
  o.w = fmaxf((acc.w + bi.w - me.w) * rsqrtf(va.w + 1e-5f) * ga.w + be.w, 0.f);
  *reinterpret_cast<float4*>(&out[(size_t)node * 256 + c]) = o;
}

// F=16 (H=1): 16 nodes per block, 16 channels each; fused softmax in-register.
__global__ __launch_bounds__(256) void k_agg16(
    const float* __restrict__ h, const float* __restrict__ bias,
    float* __restrict__ out, int n) {
  const int local = threadIdx.x >> 4;
  const int c = threadIdx.x & 15;
  const int node = blockIdx.x * 16 + local;
  if (node >= n) return;
  const float dscore = g_d[node];
  const int k0 = g_off[node];
  const int k1 = g_off[node + 1];
  float acc = 0.f;
  float den = 0.f;
  for (int k = k0; k < k1; k++) {
    const int src = g_csrc[k];
    float v = g_s[src] + dscore;
    v = (v > 0.f) ? v : 0.2f * v;
    const float al = __expf(v);
    den += al;
    acc = fmaf(al, h[(size_t)src * 16 + c], acc);
  }
  out[(size_t)node * 16 + c] = acc / den + bias[c];
}

// ---------------- host ----------------
extern "C" void kernel_launch(void* const* d_in, const int* in_sizes, int n_in,
                              void* d_out, int out_size) {
  const float* x   = (const float*)d_in[0];
  const int*   ei  = (const int*)d_in[1];       // int32 (JAX x64 disabled)
  const float* W1  = (const float*)d_in[2];
  const float* as1 = (const float*)d_in[3];
  const float* ad1 = (const float*)d_in[4];
  const float* b1  = (const float*)d_in[5];
  const float* g1  = (const float*)d_in[6];
  const float* be1 = (const float*)d_in[7];
  const float* m1  = (const float*)d_in[8];
  const float* v1  = (const float*)d_in[9];
  const float* W2  = (const float*)d_in[10];
  const float* as2 = (const float*)d_in[11];
  const float* ad2 = (const float*)d_in[12];
  const float* b2  = (const float*)d_in[13];
  const float* g2  = (const float*)d_in[14];
  const float* be2 = (const float*)d_in[15];
  const float* m2  = (const float*)d_in[16];
  const float* v2  = (const float*)d_in[17];
  const float* W3  = (const float*)d_in[18];
  const float* as3 = (const float*)d_in[19];
  const float* ad3 = (const float*)d_in[20];
  const float* b3  = (const float*)d_in[21];

  const int n  = in_sizes[0] / 128;    // 50000
  const int E  = in_sizes[1] / 2;      // 800000
  const int ET = E + n;

  float* p_h;   cudaGetSymbolAddress((void**)&p_h,   g_h);
  float* p_out; cudaGetSymbolAddress((void**)&p_out, g_out);

  const int TB = 256;
  const int edgeBlocks = (ET + TB - 1) / TB;

  // ---- CSR by dst (shared by all 3 layers) ----
  k_zero_deg<<<(n + TB - 1) / TB, TB>>>(n);
  k_count<<<edgeBlocks, TB>>>(ei, E, n);
  k_scan<<<1, 1024>>>(n);
  k_scatter<<<edgeBlocks, TB>>>(ei, E, n);

  // ---- layer 1: GAT(128 -> 64x4) + BN + ReLU ----
  {
    dim3 grid(2, (n + 127) / 128);
    gemm256_fused<<<grid, 256>>>(x, W1, p_h, as1, ad1, n, 128);
    k_agg256<<<(n + 3) / 4, 256>>>(p_h, b1, g1, be1, m1, v1, p_out, n);
  }

  // ---- layer 2: GAT(256 -> 64x4) + BN + ReLU ----
  {
    dim3 grid(2, (n + 127) / 128);
    gemm256_fused<<<grid, 256>>>(p_out, W2, p_h, as2, ad2, n, 256);
    k_agg256<<<(n + 3) / 4, 256>>>(p_h, b2, g2, be2, m2, v2, p_out, n);
  }

  // ---- layer 3: GAT(256 -> 16, single head, no concat) ----
  {
    gemm_n16_fused<<<((size_t)n * 16 + TB - 1) / TB, TB>>>(p_out, W3, p_h, as3, ad3, n);
    k_agg16<<<(n + 15) / 16, 256>>>(p_h, b3, (float*)d_out, n);
  }
}

// round 7
// speedup vs baseline: 2.9616x; 1.4094x over previous
#include <cuda_runtime.h>
#include <math.h>
#include <stdint.h>

#define NNODES 50000
#define NEDGES 800000
#define ETMAX (NEDGES + NNODES)

// ---------------- scratch (device globals; no allocation allowed) ----------
__device__ __align__(16) float g_h[(size_t)NNODES * 256];   // post-GEMM features
__device__ __align__(16) float g_out[(size_t)NNODES * 256]; // aggregated output / next input
__device__ __align__(16) float g_s[NNODES * 4];             // per (node,head) src score
__device__ __align__(16) float g_d[NNODES * 4];             // per (node,head) dst score
__device__ int   g_deg[NNODES];
__device__ int   g_off[NNODES + 1];
__device__ int   g_cur[NNODES];
__device__ int   g_csrc[ETMAX];                  // CSR-by-dst: source node

// ---------------- tf32 helpers ----------------
__device__ __forceinline__ uint32_t f2tf32(float x) {
  uint32_t u;
  asm("cvt.rna.tf32.f32 %0, %1;" : "=r"(u) : "f"(x));
  return u;
}
__device__ __forceinline__ void mma_tf32(float* c, const uint32_t* a, const uint32_t* b) {
  asm volatile(
    "mma.sync.aligned.m16n8k8.row.col.f32.tf32.tf32.f32 "
    "{%0,%1,%2,%3}, {%4,%5,%6,%7}, {%8,%9}, {%0,%1,%2,%3};"
    : "+f"(c[0]), "+f"(c[1]), "+f"(c[2]), "+f"(c[3])
    : "r"(a[0]), "r"(a[1]), "r"(a[2]), "r"(a[3]), "r"(b[0]), "r"(b[1]));
}

// ---------------- tensor-core GEMM: C[M,256] = A[M,K] @ B[K,256] ------------
// B is the original W (row-major [K][256]). Fused attention dots:
// g_s[row*4+h] = <C[row, h*64..], asrc[h*64..]>, likewise g_d.
// Grid: (2, ceil(M/128)); 256 threads (8 warps, 2x4; warp tile 64x32).
__global__ __launch_bounds__(256) void gemm_mma(
    const float* __restrict__ A, const float* __restrict__ B, float* __restrict__ C,
    const float* __restrict__ asrc, const float* __restrict__ adst, int M, int K) {
  __shared__ uint32_t As[128][20];   // stride 20: banks 20g+t -> conflict-free frags
  __shared__ uint32_t Bs[16][136];   // stride 136: banks 8k+n -> conflict-free frags
  __shared__ float s_as[256], s_ad[256];
  __shared__ float spart[128][4], dpart[128][4];

  const int tid = threadIdx.x;
  const int wid = tid >> 5, lane = tid & 31;
  const int group = lane >> 2, tid4 = lane & 3;
  const int wm = wid >> 2, wn = wid & 3;       // warp row (0..1), warp col (0..3)
  const int rowBase = blockIdx.y * 128;
  const int colBase = blockIdx.x * 128;

  s_as[tid] = asrc[tid];
  s_ad[tid] = adst[tid];

  float acc[4][4][4];
#pragma unroll
  for (int mi = 0; mi < 4; mi++)
#pragma unroll
    for (int ni = 0; ni < 4; ni++)
#pragma unroll
      for (int q = 0; q < 4; q++) acc[mi][ni][q] = 0.f;

  // gmem load maps: A 128x16 (512 float4, 2/thread), B 16x128 (512 float4, 2/thread)
  const int arow = tid >> 2, aq = tid & 3;
  const int brow = tid >> 5, bq = tid & 31;
  const bool aok0 = (rowBase + arow) < M;
  const bool aok1 = (rowBase + arow + 64) < M;

  float4 av0, av1, bv0, bv1;
  const float4 z4 = make_float4(0.f, 0.f, 0.f, 0.f);

  // prefetch first tile
  av0 = aok0 ? *reinterpret_cast<const float4*>(&A[(size_t)(rowBase + arow) * K + aq * 4]) : z4;
  av1 = aok1 ? *reinterpret_cast<const float4*>(&A[(size_t)(rowBase + arow + 64) * K + aq * 4]) : z4;
  bv0 = *reinterpret_cast<const float4*>(&B[(size_t)brow * 256 + colBase + bq * 4]);
  bv1 = *reinterpret_cast<const float4*>(&B[(size_t)(brow + 8) * 256 + colBase + bq * 4]);

  for (int k0 = 0; k0 < K; k0 += 16) {
    As[arow][aq * 4 + 0] = f2tf32(av0.x);
    As[arow][aq * 4 + 1] = f2tf32(av0.y);
    As[arow][aq * 4 + 2] = f2tf32(av0.z);
    As[arow][aq * 4 + 3] = f2tf32(av0.w);
    As[arow + 64][aq * 4 + 0] = f2tf32(av1.x);
    As[arow + 64][aq * 4 + 1] = f2tf32(av1.y);
    As[arow + 64][aq * 4 + 2] = f2tf32(av1.z);
    As[arow + 64][aq * 4 + 3] = f2tf32(av1.w);
    Bs[brow][bq * 4 + 0] = f2tf32(bv0.x);
    Bs[brow][bq * 4 + 1] = f2tf32(bv0.y);
    Bs[brow][bq * 4 + 2] = f2tf32(bv0.z);
    Bs[brow][bq * 4 + 3] = f2tf32(bv0.w);
    Bs[brow + 8][bq * 4 + 0] = f2tf32(bv1.x);
    Bs[brow + 8][bq * 4 + 1] = f2tf32(bv1.y);
    Bs[brow + 8][bq * 4 + 2] = f2tf32(bv1.z);
    Bs[brow + 8][bq * 4 + 3] = f2tf32(bv1.w);
    __syncthreads();

    if (k0 + 16 < K) {
      const int kn = k0 + 16;
      av0 = aok0 ? *reinterpret_cast<const float4*>(&A[(size_t)(rowBase + arow) * K + kn + aq * 4]) : z4;
      av1 = aok1 ? *reinterpret_cast<const float4*>(&A[(size_t)(rowBase + arow + 64) * K + kn + aq * 4]) : z4;
      bv0 = *reinterpret_cast<const float4*>(&B[(size_t)(kn + brow) * 256 + colBase + bq * 4]);
      bv1 = *reinterpret_cast<const float4*>(&B[(size_t)(kn + brow + 8) * 256 + colBase + bq * 4]);
    }

#pragma unroll
    for (int ks = 0; ks < 2; ks++) {
      uint32_t af[4][4], bf[4][2];
      const int cc = ks * 8 + tid4;
#pragma unroll
      for (int mi = 0; mi < 4; mi++) {
        const int r = wm * 64 + mi * 16 + group;
        af[mi][0] = As[r][cc];
        af[mi][1] = As[r + 8][cc];
        af[mi][2] = As[r][cc + 4];
        af[mi][3] = As[r + 8][cc + 4];
      }
#pragma unroll
      for (int ni = 0; ni < 4; ni++) {
        const int nn = wn * 32 + ni * 8 + group;
        bf[ni][0] = Bs[ks * 8 + tid4][nn];
        bf[ni][1] = Bs[ks * 8 + tid4 + 4][nn];
      }
#pragma unroll
      for (int mi = 0; mi < 4; mi++)
#pragma unroll
        for (int ni = 0; ni < 4; ni++) mma_tf32(acc[mi][ni], af[mi], bf[ni]);
    }
    __syncthreads();
  }

  // ---------------- epilogue: C stores + fused attention dots ----------------
#pragma unroll
  for (int mi = 0; mi < 4; mi++) {
    const int lr0 = wm * 64 + mi * 16 + group;  // local rows
    const int lr1 = lr0 + 8;
    const int r0 = rowBase + lr0;
    const int r1 = rowBase + lr1;
    float s0 = 0.f, d0 = 0.f, s1 = 0.f, d1 = 0.f;
#pragma unroll
    for (int ni = 0; ni < 4; ni++) {
      const int col = colBase + wn * 32 + ni * 8 + tid4 * 2;
      const float c0 = acc[mi][ni][0], c1 = acc[mi][ni][1];
      const float c2 = acc[mi][ni][2], c3 = acc[mi][ni][3];
      const float a0 = s_as[col], a1 = s_as[col + 1];
      const float e0 = s_ad[col], e1 = s_ad[col + 1];
      s0 = fmaf(c0, a0, fmaf(c1, a1, s0));
      d0 = fmaf(c0, e0, fmaf(c1, e1, d0));
      s1 = fmaf(c2, a0, fmaf(c3, a1, s1));
      d1 = fmaf(c2, e0, fmaf(c3, e1, d1));
      if (r0 < M) *reinterpret_cast<float2*>(&C[(size_t)r0 * 256 + col]) = make_float2(c0, c1);
      if (r1 < M) *reinterpret_cast<float2*>(&C[(size_t)r1 * 256 + col]) = make_float2(c2, c3);
    }
#pragma unroll
    for (int o = 1; o < 4; o <<= 1) {
      s0 += __shfl_xor_sync(0xffffffffu, s0, o);
      d0 += __shfl_xor_sync(0xffffffffu, d0, o);
      s1 += __shfl_xor_sync(0xffffffffu, s1, o);
      d1 += __shfl_xor_sync(0xffffffffu, d1, o);
    }
    if (tid4 == 0) {
      spart[lr0][wn] = s0; dpart[lr0][wn] = d0;
      spart[lr1][wn] = s1; dpart[lr1][wn] = d1;
    }
  }
  __syncthreads();
  {
    const int lrow = tid >> 1, hh = tid & 1;
    const int grow = rowBase + lrow;
    if (grow < M) {
      const float s = spart[lrow][hh * 2] + spart[lrow][hh * 2 + 1];
      const float d = dpart[lrow][hh * 2] + dpart[lrow][hh * 2 + 1];
      const int head = blockIdx.x * 2 + hh;
      g_s[grow * 4 + head] = s;
      g_d[grow * 4 + head] = d;
    }
  }
}

// ---------------- GEMM layer 3: N=16, K=256, fused attn (fp32) -------------
__global__ __launch_bounds__(256) void gemm_n16_fused(
    const float* __restrict__ A, const float* __restrict__ B, float* __restrict__ C,
    const float* __restrict__ as3, const float* __restrict__ ad3, int M) {
  const int t = blockIdx.x * blockDim.x + threadIdx.x;
  const int row = t >> 4;
  const int nc = t & 15;
  if (row >= M) return;
  const float* a = A + (size_t)row * 256;
  float acc = 0.f;
#pragma unroll 8
  for (int k = 0; k < 256; k += 4) {
    const float4 av = *reinterpret_cast<const float4*>(a + k);
    acc = fmaf(av.x, B[(k + 0) * 16 + nc], acc);
    acc = fmaf(av.y, B[(k + 1) * 16 + nc], acc);
    acc = fmaf(av.z, B[(k + 2) * 16 + nc], acc);
    acc = fmaf(av.w, B[(k + 3) * 16 + nc], acc);
  }
  C[(size_t)row * 16 + nc] = acc;
  float sv = acc * as3[nc];
  float dv = acc * ad3[nc];
#pragma unroll
  for (int o = 1; o < 16; o <<= 1) {
    sv += __shfl_xor_sync(0xffffffffu, sv, o);
    dv += __shfl_xor_sync(0xffffffffu, dv, o);
  }
  if (nc == 0) { g_s[row] = sv; g_d[row] = dv; }
}

// ---------------- CSR build --------------------------------------------------
__global__ void k_zero_deg(int n) {
  int i = blockIdx.x * blockDim.x + threadIdx.x;
  if (i < n) g_deg[i] = 0;
}

__global__ void k_count(const int* __restrict__ ei, int E, int n) {
  int e = blockIdx.x * blockDim.x + threadIdx.x;
  if (e >= E + n) return;
  int dst = (e < E) ? ei[E + e] : (e - E);
  atomicAdd(&g_deg[dst], 1);
}

__global__ void k_scan(int n) {   // 1024 threads, shuffle scan
  __shared__ int wsum[32];
  __shared__ int wexcl[32];
  __shared__ int carry, total;
  const int tid = threadIdx.x;
  const int lane = tid & 31;
  const int wid = tid >> 5;
  if (tid == 0) carry = 0;
  __syncthreads();
  for (int base = 0; base < n; base += 1024) {
    const int i = base + tid;
    const int v = (i < n) ? g_deg[i] : 0;
    int s = v;
#pragma unroll
    for (int o = 1; o < 32; o <<= 1) {
      int tt = __shfl_up_sync(0xffffffffu, s, o);
      if (lane >= o) s += tt;
    }
    if (lane == 31) wsum[wid] = s;
    __syncthreads();
    if (wid == 0) {
      int w = wsum[lane];
      int ws = w;
#pragma unroll
      for (int o = 1; o < 32; o <<= 1) {
        int tt = __shfl_up_sync(0xffffffffu, ws, o);
        if (lane >= o) ws += tt;
      }
      wexcl[lane] = ws - w;
      if (lane == 31) total = ws;
    }
    __syncthreads();
    const int excl = carry + wexcl[wid] + (s - v);
    if (i < n) { g_off[i] = excl; g_cur[i] = excl; }
    __syncthreads();
    if (tid == 0) carry += total;
    __syncthreads();
  }
  if (tid == 0) g_off[n] = carry;
}

__global__ void k_scatter(const int* __restrict__ ei, int E, int n) {
  int e = blockIdx.x * blockDim.x + threadIdx.x;
  if (e >= E + n) return;
  int src, dst;
  if (e < E) { src = ei[e]; dst = ei[E + e]; }
  else       { src = dst = e - E; }
  const int pos = atomicAdd(&g_cur[dst], 1);
  g_csrc[pos] = src;
}

// ---------------- fully fused aggregation -----------------------------------
__global__ __launch_bounds__(256) void k_agg256(
    const float* __restrict__ h,
    const float* __restrict__ bias, const float* __restrict__ gamma,
    const float* __restrict__ beta, const float* __restrict__ mean,
    const float* __restrict__ var, float* __restrict__ out, int n) {
  const int grp = threadIdx.x >> 6;
  const int c4  = threadIdx.x & 63;
  const int node = blockIdx.x * 4 + grp;
  if (node >= n) return;
  const int c = c4 * 4;
  const int hd = c >> 6;
  const float dscore = g_d[node * 4 + hd];
  const int k0 = g_off[node];
  const int k1 = g_off[node + 1];
  float4 acc = make_float4(0.f, 0.f, 0.f, 0.f);
  float den = 0.f;
  int k = k0;
  int src_n = (k < k1) ? g_csrc[k] : 0;
  while (k < k1) {
    const int src = src_n;
    float v = g_s[src * 4 + hd] + dscore;
    const float4 hv = *reinterpret_cast<const float4*>(&h[(size_t)src * 256 + c]);
    k++;
    if (k < k1) src_n = g_csrc[k];
    v = (v > 0.f) ? v : 0.2f * v;       // leaky relu
    const float al = __expf(v);         // unshifted exp: scores are O(1)
    den += al;
    acc.x = fmaf(al, hv.x, acc.x);
    acc.y = fmaf(al, hv.y, acc.y);
    acc.z = fmaf(al, hv.z, acc.z);
    acc.w = fmaf(al, hv.w, acc.w);
  }
  const float invden = 1.f / den;
  acc.x *= invden; acc.y *= invden; acc.z *= invden; acc.w *= invden;
  const float4 bi = *reinterpret_cast<const float4*>(&bias[c]);
  const float4 ga = *reinterpret_cast<const float4*>(&gamma[c]);
  const float4 be = *reinterpret_cast<const float4*>(&beta[c]);
  const float4 me = *reinterpret_cast<const float4*>(&mean[c]);
  const float4 va = *reinterpret_cast<const float4*>(&var[c]);
  float4 o;
  o.x = fmaxf((acc.x + bi.x - me.x) * rsqrtf(va.x + 1e-5f) * ga.x + be.x, 0.f);
  o.y = fmaxf((acc.y + bi.y - me.y) * rsqrtf(va.y + 1e-5f) * ga.y + be.y, 0.f);
  o.z = fmaxf((acc.z + bi.z - me.z) * rsqrtf(va.z + 1e-5f) * ga.z + be.z, 0.f);
  o.w = fmaxf((acc.w + bi.w - me.w) * rsqrtf(va.w + 1e-5f) * ga.w + be.w, 0.f);
  *reinterpret_cast<float4*>(&out[(size_t)node * 256 + c]) = o;
}

__global__ __launch_bounds__(256) void k_agg16(
    const float* __restrict__ h, const float* __restrict__ bias,
    float* __restrict__ out, int n) {
  const int local = threadIdx.x >> 4;
  const int c = threadIdx.x & 15;
  const int node = blockIdx.x * 16 + local;
  if (node >= n) return;
  const float dscore = g_d[node];
  const int k0 = g_off[node];
  const int k1 = g_off[node + 1];
  float acc = 0.f;
  float den = 0.f;
  for (int k = k0; k < k1; k++) {
    const int src = g_csrc[k];
    float v = g_s[src] + dscore;
    v = (v > 0.f) ? v : 0.2f * v;
    const float al = __expf(v);
    den += al;
    acc = fmaf(al, h[(size_t)src * 16 + c], acc);
  }
  out[(size_t)node * 16 + c] = acc / den + bias[c];
}

// ---------------- host ----------------
extern "C" void kernel_launch(void* const* d_in, const int* in_sizes, int n_in,
                              void* d_out, int out_size) {
  const float* x   = (const float*)d_in[0];
  const int*   ei  = (const int*)d_in[1];       // int32 (JAX x64 disabled)
  const float* W1  = (const float*)d_in[2];
  const float* as1 = (const float*)d_in[3];
  const float* ad1 = (const float*)d_in[4];
  const float* b1  = (const float*)d_in[5];
  const float* g1  = (const float*)d_in[6];
  const float* be1 = (const float*)d_in[7];
  const float* m1  = (const float*)d_in[8];
  const float* v1  = (const float*)d_in[9];
  const float* W2  = (const float*)d_in[10];
  const float* as2 = (const float*)d_in[11];
  const float* ad2 = (const float*)d_in[12];
  const float* b2  = (const float*)d_in[13];
  const float* g2  = (const float*)d_in[14];
  const float* be2 = (const float*)d_in[15];
  const float* m2  = (const float*)d_in[16];
  const float* v2  = (const float*)d_in[17];
  const float* W3  = (const float*)d_in[18];
  const float* as3 = (const float*)d_in[19];
  const float* ad3 = (const float*)d_in[20];
  const float* b3  = (const float*)d_in[21];

  const int n  = in_sizes[0] / 128;    // 50000
  const int E  = in_sizes[1] / 2;      // 800000
  const int ET = E + n;

  float* p_h;   cudaGetSymbolAddress((void**)&p_h,   g_h);
  float* p_out; cudaGetSymbolAddress((void**)&p_out, g_out);

  const int TB = 256;
  const int edgeBlocks = (ET + TB - 1) / TB;

  // ---- CSR by dst (shared by all 3 layers) ----
  k_zero_deg<<<(n + TB - 1) / TB, TB>>>(n);
  k_count<<<edgeBlocks, TB>>>(ei, E, n);
  k_scan<<<1, 1024>>>(n);
  k_scatter<<<edgeBlocks, TB>>>(ei, E, n);

  dim3 mmaGrid(2, (n + 127) / 128);

  // ---- layer 1: GAT(128 -> 64x4) + BN + ReLU ----
  gemm_mma<<<mmaGrid, 256>>>(x, W1, p_h, as1, ad1, n, 128);
  k_agg256<<<(n + 3) / 4, 256>>>(p_h, b1, g1, be1, m1, v1, p_out, n);

  // ---- layer 2: GAT(256 -> 64x4) + BN + ReLU ----
  gemm_mma<<<mmaGrid, 256>>>(p_out, W2, p_h, as2, ad2, n, 256);
  k_agg256<<<(n + 3) / 4, 256>>>(p_h, b2, g2, be2, m2, v2, p_out, n);

  // ---- layer 3: GAT(256 -> 16, single head, no concat) ----
  gemm_n16_fused<<<((size_t)n * 16 + TB - 1) / TB, TB>>>(p_out, W3, p_h, as3, ad3, n);
  k_agg16<<<(n + 15) / 16, 256>>>(p_h, b3, (float*)d_out, n);
}